// round 5
// baseline (speedup 1.0000x reference)
#include <cuda_runtime.h>

#define BATCH 32
#define SEQ   4096

// ---------------- scratch (device globals; no allocation) ----------------
__device__ __align__(16) float g_h1[BATCH][4097][64];   // harmony conv1 out [b][pos][c]
__device__ __align__(16) float g_m1[BATCH][4096][64];   // melody  conv1 out
__device__ __align__(16) float g_r1[BATCH][2048][32];   // rhythm  conv1 out
__device__ __align__(16) float g_d1[BATCH][4097][16];   // dynamics conv1 out

// transposed first-layer weights: [k][token][o]
__device__ __align__(16) float g_wT_h[12][128][64];
__device__ __align__(16) float g_wT_m[5][128][64];
__device__ __align__(16) float g_wT_d[4][6][16];
__device__ __align__(16) float g_wT_r[8][32];

// transposed second-layer weights: [o][k][c]
__device__ __align__(16) float g_w2_h[32][8][64];
__device__ __align__(16) float g_w2_m[32][3][64];
__device__ __align__(16) float g_w2_r[64][4][32];
__device__ __align__(16) float g_w2_d[16][3][16];

// partial pooled sums
__device__ float g_part_r[BATCH][8][64];    // [b][chunk of 128 l][o]
__device__ float g_part_h[BATCH][16][32];
__device__ float g_part_m[BATCH][32][32];
__device__ float g_dpool [BATCH][128][16];  // [b][q][o]
__device__ __align__(16) float g_feats[BATCH][512];

// ---------------- weight prep (transpose, tiny) ----------------
__global__ void prep_kernel(const float* __restrict__ r1w, const float* __restrict__ r2w,
                            const float* __restrict__ h1w, const float* __restrict__ h2w,
                            const float* __restrict__ m1w, const float* __restrict__ m2w,
                            const float* __restrict__ d1w, const float* __restrict__ d2w) {
    int stride = gridDim.x * blockDim.x;
    int tid = blockIdx.x * blockDim.x + threadIdx.x;
    for (int i = tid; i < 64*128*12; i += stride) {
        int o = i / (128*12), r = i % (128*12), t = r / 12, k = r % 12;
        g_wT_h[k][t][o] = h1w[i];
    }
    for (int i = tid; i < 64*128*5; i += stride) {
        int o = i / 640, r = i % 640, t = r / 5, k = r % 5;
        g_wT_m[k][t][o] = m1w[i];
    }
    for (int i = tid; i < 16*6*4; i += stride) {
        int o = i / 24, r = i % 24, v = r / 4, k = r % 4;
        g_wT_d[k][v][o] = d1w[i];
    }
    for (int i = tid; i < 32*8; i += stride) {
        int o = i / 8, k = i % 8;
        g_wT_r[k][o] = r1w[i];
    }
    for (int i = tid; i < 32*64*8; i += stride) {
        int o = i / 512, r = i % 512, c = r / 8, k = r % 8;
        g_w2_h[o][k][c] = h2w[i];
    }
    for (int i = tid; i < 32*64*3; i += stride) {
        int o = i / 192, r = i % 192, c = r / 3, k = r % 3;
        g_w2_m[o][k][c] = m2w[i];
    }
    for (int i = tid; i < 64*32*4; i += stride) {
        int o = i / 128, r = i % 128, c = r / 4, k = r % 4;
        g_w2_r[o][k][c] = r2w[i];
    }
    for (int i = tid; i < 16*16*3; i += stride) {
        int o = i / 48, r = i % 48, c = r / 3, k = r % 3;
        g_w2_d[o][k][c] = d2w[i];
    }
}

// ---------------- rhythm conv1: binary input, stride 2, pad 3, K=8, 1->32 ch ----------------
__global__ void __launch_bounds__(256) rhythm1_kernel(const int* __restrict__ tok,
                                                      const float* __restrict__ r1b) {
    __shared__ float tsv[70];
    int b = blockIdx.y;
    int base = blockIdx.x * 32;             // 32 output positions per block
    int tid = threadIdx.x;
    if (tid < 70) {
        int p = 2*base - 3 + tid;
        float v = 0.f;
        if (p >= 0 && p < SEQ) {
            int t = tok[b*SEQ + p];
            v = (t >= 256 && t < 768) ? 1.f : 0.f;
        }
        tsv[tid] = v;
    }
    __syncthreads();
    int oq = tid & 7, po = tid >> 3;
    int pos = base + po;
    float4 acc = __ldg(reinterpret_cast<const float4*>(r1b) + oq);
    #pragma unroll
    for (int k = 0; k < 8; k++) {
        float t = tsv[2*po + k];
        float4 w = *reinterpret_cast<const float4*>(&g_wT_r[k][oq*4]);
        acc.x = fmaf(t, w.x, acc.x);
        acc.y = fmaf(t, w.y, acc.y);
        acc.z = fmaf(t, w.z, acc.z);
        acc.w = fmaf(t, w.w, acc.w);
    }
    acc.x = fmaxf(acc.x, 0.f); acc.y = fmaxf(acc.y, 0.f);
    acc.z = fmaxf(acc.z, 0.f); acc.w = fmaxf(acc.w, 0.f);
    *reinterpret_cast<float4*>(&g_r1[b][pos][oq*4]) = acc;
}

// ---------------- harmony conv1 via gather: K=12, pad 6, 128(one-hot)->64 ----------------
__global__ void __launch_bounds__(256) h1_kernel(const int* __restrict__ tok,
                                                 const float* __restrict__ h1b) {
    __shared__ int stok[27];
    int b = blockIdx.y;
    int base = blockIdx.x * 16;
    int tid = threadIdx.x;
    if (tid < 27) {
        int p = base - 6 + tid;
        stok[tid] = (p >= 0 && p < SEQ) ? tok[b*SEQ + p] : -1;
    }
    __syncthreads();
    int o4 = tid & 15, po = tid >> 4;
    int pos = base + po;
    if (pos >= 4097) return;
    float4 acc = __ldg(reinterpret_cast<const float4*>(h1b) + o4);
    #pragma unroll
    for (int k = 0; k < 12; k++) {
        int t = stok[po + k];
        if ((unsigned)t < 128u) {
            float4 w = *reinterpret_cast<const float4*>(&g_wT_h[k][t][o4*4]);
            acc.x += w.x; acc.y += w.y; acc.z += w.z; acc.w += w.w;
        }
    }
    acc.x = fmaxf(acc.x, 0.f); acc.y = fmaxf(acc.y, 0.f);
    acc.z = fmaxf(acc.z, 0.f); acc.w = fmaxf(acc.w, 0.f);
    *reinterpret_cast<float4*>(&g_h1[b][pos][o4*4]) = acc;
}

// ---------------- melody conv1 via gather: K=5, pad 2, 128(one-hot)->64 ----------------
__global__ void __launch_bounds__(256) m1_kernel(const int* __restrict__ tok,
                                                 const float* __restrict__ m1b) {
    __shared__ int stok[20];
    int b = blockIdx.y;
    int base = blockIdx.x * 16;
    int tid = threadIdx.x;
    if (tid < 20) {
        int p = base - 2 + tid;
        stok[tid] = (p >= 0 && p < SEQ) ? tok[b*SEQ + p] : -1;
    }
    __syncthreads();
    int o4 = tid & 15, po = tid >> 4;
    int pos = base + po;                    // always < 4096
    float4 acc = __ldg(reinterpret_cast<const float4*>(m1b) + o4);
    #pragma unroll
    for (int k = 0; k < 5; k++) {
        int t = stok[po + k];
        if ((unsigned)t < 128u) {
            float4 w = *reinterpret_cast<const float4*>(&g_wT_m[k][t][o4*4]);
            acc.x += w.x; acc.y += w.y; acc.z += w.z; acc.w += w.w;
        }
    }
    acc.x = fmaxf(acc.x, 0.f); acc.y = fmaxf(acc.y, 0.f);
    acc.z = fmaxf(acc.z, 0.f); acc.w = fmaxf(acc.w, 0.f);
    *reinterpret_cast<float4*>(&g_m1[b][pos][o4*4]) = acc;
}

// ---------------- dynamics conv1 via gather: K=4, pad 2, 6(one-hot)->16 ----------------
__global__ void __launch_bounds__(256) d1_kernel(const int* __restrict__ tok,
                                                 const float* __restrict__ d1b) {
    __shared__ signed char sv[260];
    int b = blockIdx.y;
    int base = blockIdx.x * 256;
    int tid = threadIdx.x;
    for (int i = tid; i < 260; i += 256) {
        int p = base - 2 + i;
        int v = -1;
        if (p >= 0 && p < SEQ) {
            int t = tok[b*SEQ + p];
            if (t >= 768) v = min(t - 768, 5);
        }
        sv[i] = (signed char)v;
    }
    __syncthreads();
    int pos = base + tid;
    if (pos >= 4097) return;
    const float4* bb = reinterpret_cast<const float4*>(d1b);
    float4 a0 = __ldg(bb + 0), a1 = __ldg(bb + 1), a2 = __ldg(bb + 2), a3 = __ldg(bb + 3);
    #pragma unroll
    for (int k = 0; k < 4; k++) {
        int v = sv[tid + k];
        if (v >= 0) {
            const float4* w = reinterpret_cast<const float4*>(&g_wT_d[k][v][0]);
            float4 w0 = w[0], w1 = w[1], w2 = w[2], w3 = w[3];
            a0.x += w0.x; a0.y += w0.y; a0.z += w0.z; a0.w += w0.w;
            a1.x += w1.x; a1.y += w1.y; a1.z += w1.z; a1.w += w1.w;
            a2.x += w2.x; a2.y += w2.y; a2.z += w2.z; a2.w += w2.w;
            a3.x += w3.x; a3.y += w3.y; a3.z += w3.z; a3.w += w3.w;
        }
    }
    a0.x=fmaxf(a0.x,0.f); a0.y=fmaxf(a0.y,0.f); a0.z=fmaxf(a0.z,0.f); a0.w=fmaxf(a0.w,0.f);
    a1.x=fmaxf(a1.x,0.f); a1.y=fmaxf(a1.y,0.f); a1.z=fmaxf(a1.z,0.f); a1.w=fmaxf(a1.w,0.f);
    a2.x=fmaxf(a2.x,0.f); a2.y=fmaxf(a2.y,0.f); a2.z=fmaxf(a2.z,0.f); a2.w=fmaxf(a2.w,0.f);
    a3.x=fmaxf(a3.x,0.f); a3.y=fmaxf(a3.y,0.f); a3.z=fmaxf(a3.z,0.f); a3.w=fmaxf(a3.w,0.f);
    float4* dst = reinterpret_cast<float4*>(&g_d1[b][pos][0]);
    dst[0] = a0; dst[1] = a1; dst[2] = a2; dst[3] = a3;
}

// ---------------- register-tiled dense conv2, fused with pooling partial sums ----------------
// block handles one (b, chunk of 128 output l); warp lane = 4-l tile; warp id = 8-o tile.
// Writes per-(chunk, o) raw ReLU sums; normalization happens in final kernel.
template<int C4, int K, int STRIDE, int PAD, int LIN>
__device__ __forceinline__ void conv2_body(const float* __restrict__ x,
                                           const float* __restrict__ w,
                                           const float* __restrict__ bias,
                                           float* __restrict__ part_row) {
    constexpr int WIN = 3 * STRIDE + K;
    const int lane = threadIdx.x & 31;
    const int ot   = threadIdx.x >> 5;
    const int obase = ot * 8;
    const int l0 = blockIdx.x * 128 + lane * 4;
    const int pbase = STRIDE * l0 - PAD;

    float acc[8][4];
    #pragma unroll
    for (int o = 0; o < 8; o++)
        #pragma unroll
        for (int d = 0; d < 4; d++) acc[o][d] = 0.f;

    const float4* xp  = reinterpret_cast<const float4*>(x);
    const float4* wp0 = reinterpret_cast<const float4*>(w);
    for (int c4 = 0; c4 < C4; c4++) {
        float4 in[WIN];
        #pragma unroll
        for (int r = 0; r < WIN; r++) {
            int p = pbase + r;
            float4 v;
            if (p >= 0 && p < LIN) v = __ldg(xp + (size_t)p * C4 + c4);
            else v = make_float4(0.f, 0.f, 0.f, 0.f);
            in[r] = v;
        }
        #pragma unroll
        for (int o = 0; o < 8; o++) {
            const float4* wp = wp0 + (size_t)(obase + o) * K * C4 + c4;
            #pragma unroll
            for (int k = 0; k < K; k++) {
                float4 ww = __ldg(wp + k * C4);
                #pragma unroll
                for (int d = 0; d < 4; d++) {
                    float4 xx = in[STRIDE * d + k];
                    acc[o][d] = fmaf(ww.x, xx.x, acc[o][d]);
                    acc[o][d] = fmaf(ww.y, xx.y, acc[o][d]);
                    acc[o][d] = fmaf(ww.z, xx.z, acc[o][d]);
                    acc[o][d] = fmaf(ww.w, xx.w, acc[o][d]);
                }
            }
        }
    }
    #pragma unroll
    for (int o = 0; o < 8; o++) {
        float bo = __ldg(bias + obase + o);
        float s = fmaxf(acc[o][0] + bo, 0.f) + fmaxf(acc[o][1] + bo, 0.f)
                + fmaxf(acc[o][2] + bo, 0.f) + fmaxf(acc[o][3] + bo, 0.f);
        #pragma unroll
        for (int off = 16; off > 0; off >>= 1)
            s += __shfl_down_sync(0xffffffffu, s, off);
        if (lane == 0) part_row[obase + o] = s;
    }
}

__global__ void __launch_bounds__(256) r2_kernel(const float* __restrict__ bias) {
    int b = blockIdx.y;
    conv2_body<8, 4, 2, 1, 2048>(&g_r1[b][0][0], &g_w2_r[0][0][0], bias,
                                 &g_part_r[b][blockIdx.x][0]);
}
__global__ void __launch_bounds__(128) h2_kernel(const float* __restrict__ bias) {
    int b = blockIdx.y;
    conv2_body<16, 8, 2, 3, 4097>(&g_h1[b][0][0], &g_w2_h[0][0][0], bias,
                                  &g_part_h[b][blockIdx.x][0]);
}
__global__ void __launch_bounds__(128) m2_kernel(const float* __restrict__ bias) {
    int b = blockIdx.y;
    conv2_body<16, 3, 1, 1, 4096>(&g_m1[b][0][0], &g_w2_m[0][0][0], bias,
                                  &g_part_m[b][blockIdx.x][0]);
}

// ---------------- dynamics conv2 + adaptive pool (variable bins, L=4097 -> 128) ----------------
__global__ void __launch_bounds__(64) d2pool_kernel(const float* __restrict__ d2b) {
    int b = blockIdx.y, q = blockIdx.x;
    int tid = threadIdx.x;
    int o = tid >> 2, j = tid & 3;
    int s0 = (q * 4097) >> 7;
    int e0 = ((q + 1) * 4097 + 127) >> 7;

    float4 w[3][4];
    #pragma unroll
    for (int k = 0; k < 3; k++)
        #pragma unroll
        for (int c4 = 0; c4 < 4; c4++)
            w[k][c4] = *reinterpret_cast<const float4*>(&g_w2_d[o][k][c4*4]);
    float bo = __ldg(d2b + o);
    const float4* xp = reinterpret_cast<const float4*>(&g_d1[b][0][0]);

    float sum = 0.f;
    for (int l = s0 + j; l < e0; l += 4) {
        float acc = bo;
        #pragma unroll
        for (int k = 0; k < 3; k++) {
            int p = l - 1 + k;
            if (p >= 0 && p < 4097) {
                #pragma unroll
                for (int c4 = 0; c4 < 4; c4++) {
                    float4 v = __ldg(xp + (size_t)p * 4 + c4);
                    acc = fmaf(v.x, w[k][c4].x, acc);
                    acc = fmaf(v.y, w[k][c4].y, acc);
                    acc = fmaf(v.z, w[k][c4].z, acc);
                    acc = fmaf(v.w, w[k][c4].w, acc);
                }
            }
        }
        sum += fmaxf(acc, 0.f);
    }
    sum += __shfl_down_sync(0xffffffffu, sum, 2);
    sum += __shfl_down_sync(0xffffffffu, sum, 1);
    if (j == 0) g_dpool[b][q][o] = sum / (float)(e0 - s0);
}

// ---------------- second-stage pooling + FC ----------------
__global__ void __launch_bounds__(256) final_kernel(const float* __restrict__ fcw,
                                                    const float* __restrict__ fcb) {
    __shared__ float comb[512];
    int b = blockIdx.x, tid = threadIdx.x;
    for (int idx = tid; idx < 512; idx += 256) {
        float v;
        if (idx < 128) {                       // rhythm: mean over 512 l of ch i/2
            int o = idx >> 1, h = idx & 1; float s = 0.f;
            #pragma unroll
            for (int c = 0; c < 4; c++) s += g_part_r[b][h*4 + c][o];
            v = s * (1.f / 512.f);
        } else if (idx < 256) {                // harmony: mean over 512 l of ch i/4
            int i = idx - 128; int o = i >> 2, qk = i & 3; float s = 0.f;
            #pragma unroll
            for (int c = 0; c < 4; c++) s += g_part_h[b][qk*4 + c][o];
            v = s * (1.f / 512.f);
        } else if (idx < 384) {                // melody: mean over 1024 l of ch i/4
            int i = idx - 256; int o = i >> 2, qk = i & 3; float s = 0.f;
            #pragma unroll
            for (int c = 0; c < 8; c++) s += g_part_m[b][qk*8 + c][o];
            v = s * (1.f / 1024.f);
        } else {                               // dynamics: mean over 16 dpool bins of ch i/8
            int i = idx - 384; int o = i >> 3, pk = i & 7; float s = 0.f;
            #pragma unroll
            for (int c = 0; c < 16; c++) s += g_dpool[b][pk*16 + c][o];
            v = s * (1.f / 16.f);
        }
        comb[idx] = v;
    }
    __syncthreads();
    const float4* cw = reinterpret_cast<const float4*>(comb);
    for (int j = tid; j < 512; j += 256) {
        float acc = __ldg(fcb + j);
        const float4* wr = reinterpret_cast<const float4*>(fcw + (size_t)j * 512);
        #pragma unroll 4
        for (int i4 = 0; i4 < 128; i4++) {
            float4 w = __ldg(wr + i4);
            float4 c = cw[i4];
            acc = fmaf(w.x, c.x, acc);
            acc = fmaf(w.y, c.y, acc);
            acc = fmaf(w.z, c.z, acc);
            acc = fmaf(w.w, c.w, acc);
        }
        g_feats[b][j] = acc;
    }
}

// ---------------- broadcast feats -> out[b][s][512] (256MB write, the true floor) ----------------
__global__ void __launch_bounds__(256) broadcast_kernel(float4* __restrict__ out) {
    const float4* f = reinterpret_cast<const float4*>(&g_feats[0][0]);
    const int64_t total = (int64_t)BATCH * SEQ * 128;
    int64_t stride = (int64_t)gridDim.x * blockDim.x;
    for (int64_t idx = (int64_t)blockIdx.x * blockDim.x + threadIdx.x; idx < total; idx += stride) {
        int j4 = (int)(idx & 127);
        int b  = (int)(idx >> 19);             // / (4096*128)
        out[idx] = __ldg(f + b * 128 + j4);
    }
}

// ---------------- launch ----------------
extern "C" void kernel_launch(void* const* d_in, const int* in_sizes, int n_in,
                              void* d_out, int out_size) {
    const int*   tok = (const int*)d_in[0];
    const float* r1w = (const float*)d_in[1];
    const float* r1b = (const float*)d_in[2];
    const float* r2w = (const float*)d_in[3];
    const float* r2b = (const float*)d_in[4];
    const float* h1w = (const float*)d_in[5];
    const float* h1b = (const float*)d_in[6];
    const float* h2w = (const float*)d_in[7];
    const float* h2b = (const float*)d_in[8];
    const float* m1w = (const float*)d_in[9];
    const float* m1b = (const float*)d_in[10];
    const float* m2w = (const float*)d_in[11];
    const float* m2b = (const float*)d_in[12];
    const float* d1w = (const float*)d_in[13];
    const float* d1b = (const float*)d_in[14];
    const float* d2w = (const float*)d_in[15];
    const float* d2b = (const float*)d_in[16];
    const float* fcw = (const float*)d_in[17];
    const float* fcb = (const float*)d_in[18];

    prep_kernel<<<96, 256>>>(r1w, r2w, h1w, h2w, m1w, m2w, d1w, d2w);

    rhythm1_kernel<<<dim3(64, BATCH), 256>>>(tok, r1b);
    h1_kernel<<<dim3(257, BATCH), 256>>>(tok, h1b);
    m1_kernel<<<dim3(256, BATCH), 256>>>(tok, m1b);
    d1_kernel<<<dim3(17, BATCH), 256>>>(tok, d1b);

    r2_kernel<<<dim3(8,  BATCH), 256>>>(r2b);
    h2_kernel<<<dim3(16, BATCH), 128>>>(h2b);
    m2_kernel<<<dim3(32, BATCH), 128>>>(m2b);
    d2pool_kernel<<<dim3(128, BATCH), 64>>>(d2b);

    final_kernel<<<BATCH, 256>>>(fcw, fcb);
    broadcast_kernel<<<8192, 256>>>((float4*)d_out);
}